// round 10
// baseline (speedup 1.0000x reference)
#include <cuda_runtime.h>
#include <cuda_fp16.h>
#include <math.h>
#include <stdint.h>

#define NB    4
#define NC    256
#define NTOK  4096
#define NHEAD 4
#define DH    32
#define HID   128
#define NQKV  384
#define CPG   8

// Q pre-scale: DH^-0.5 * log2(e)
#define QSCL 0.2550662672f

// -------- scratch --------
__device__ __half g_q[(size_t)NB * NHEAD * NTOK * DH];   // [b][h][tok][f] token-major, pre-scaled
__device__ __half g_k[(size_t)NB * NHEAD * NTOK * DH];   // [b][h][tok][f] token-major
__device__ __half g_v[(size_t)NB * HID * NTOK];          // [b][f][tok]   f-major
__device__ float  g_att[(size_t)NB * HID * NTOK];        // fp32 f-major
__device__ float  g_xn [(size_t)NB * NC * NTOK];         // normalized x, rna-tf32

// ---------- helpers ----------
__device__ __forceinline__ uint32_t f2tf(float f) {
    uint32_t u; asm("cvt.rna.tf32.f32 %0, %1;" : "=r"(u) : "f"(f)); return u;
}
__device__ __forceinline__ float rtf(float f) { return __uint_as_float(f2tf(f)); }
__device__ __forceinline__ void mma_tf32(float c[4], const uint32_t a[4], uint32_t b0, uint32_t b1) {
    asm volatile("mma.sync.aligned.m16n8k8.row.col.f32.tf32.tf32.f32 "
                 "{%0,%1,%2,%3}, {%4,%5,%6,%7}, {%8,%9}, {%0,%1,%2,%3};"
                 : "+f"(c[0]), "+f"(c[1]), "+f"(c[2]), "+f"(c[3])
                 : "r"(a[0]), "r"(a[1]), "r"(a[2]), "r"(a[3]), "r"(b0), "r"(b1));
}
__device__ __forceinline__ void mma_f16(float c[4], const uint32_t a[4], uint32_t b0, uint32_t b1) {
    asm volatile("mma.sync.aligned.m16n8k16.row.col.f32.f16.f16.f32 "
                 "{%0,%1,%2,%3}, {%4,%5,%6,%7}, {%8,%9}, {%0,%1,%2,%3};"
                 : "+f"(c[0]), "+f"(c[1]), "+f"(c[2]), "+f"(c[3])
                 : "r"(a[0]), "r"(a[1]), "r"(a[2]), "r"(a[3]), "r"(b0), "r"(b1));
}
__device__ __forceinline__ void cpa16(uint32_t dst, const void* src) {
    asm volatile("cp.async.ca.shared.global [%0], [%1], 16;" :: "r"(dst), "l"(src));
}
#define CPA_COMMIT() asm volatile("cp.async.commit_group;")

// ================= GroupNorm: stats + write normalized x (rna-tf32) =================
__global__ void __launch_bounds__(256) k_gnstats(const float* __restrict__ x,
                                                 const float* __restrict__ gw,
                                                 const float* __restrict__ gb)
{
    const int b = blockIdx.x >> 5;
    const int g = blockIdx.x & 31;
    const size_t base = ((size_t)(b * NC + g * CPG)) * NTOK;
    const float4* p4 = (const float4*)(x + base);
    float4* o4 = (float4*)(g_xn + base);
    float s = 0.f, s2 = 0.f;
    for (int i = threadIdx.x; i < 8192; i += 256) {
        float4 v = p4[i];
        s  += (v.x + v.y) + (v.z + v.w);
        s2 += v.x * v.x + v.y * v.y + v.z * v.z + v.w * v.w;
    }
    #pragma unroll
    for (int off = 16; off; off >>= 1) {
        s  += __shfl_xor_sync(0xffffffffu, s,  off);
        s2 += __shfl_xor_sync(0xffffffffu, s2, off);
    }
    __shared__ float ws[8], ws2[8];
    __shared__ float al8[CPG], be8[CPG];
    const int w = threadIdx.x >> 5;
    if ((threadIdx.x & 31) == 0) { ws[w] = s; ws2[w] = s2; }
    __syncthreads();
    if (threadIdx.x < CPG) {
        float t = 0.f, t2 = 0.f;
        #pragma unroll
        for (int i = 0; i < 8; i++) { t += ws[i]; t2 += ws2[i]; }
        float mean = t * (1.f / 32768.f);
        float var  = t2 * (1.f / 32768.f) - mean * mean;
        float sr = rsqrtf(var + 1e-5f);
        int c = g * CPG + threadIdx.x;
        float a = gw[c] * sr;
        al8[threadIdx.x] = a;
        be8[threadIdx.x] = gb[c] - mean * a;
    }
    __syncthreads();
    for (int i = threadIdx.x; i < 8192; i += 256) {
        int cl = i >> 10;
        float a = al8[cl], bb = be8[cl];
        float4 v = p4[i];
        o4[i] = make_float4(rtf(fmaf(v.x, a, bb)), rtf(fmaf(v.y, a, bb)),
                            rtf(fmaf(v.z, a, bb)), rtf(fmaf(v.w, a, bb)));
    }
}

// ================= pipelined tf32 GEMM (unchanged from R9) =================
template<int MTOT, int KTOT, int OMODE>
__global__ void __launch_bounds__(256) k_gemm(const float* __restrict__ A,
                                              const float* __restrict__ Bg,
                                              float* __restrict__ Cg,
                                              const float* __restrict__ bias)
{
    constexpr int NK = KTOT / 32;
    const int b  = blockIdx.z;
    const int m0 = blockIdx.y * 128;
    const int n0 = blockIdx.x * 64;
    __shared__ float As[128][36];
    __shared__ float Xs[2][32][72];
    const float* Bb = Bg + (size_t)b * KTOT * NTOK;
    const int tid = threadIdx.x, w = tid >> 5, lane = tid & 31;
    const int g = lane >> 2, t = lane & 3;
    const int wm = (w >> 1) * 32, wn = (w & 1) * 32;
    const uint32_t xsbase = (uint32_t)__cvta_generic_to_shared(&Xs[0][0][0]);
    const int kcA = tid >> 4, ncA = (tid & 15) << 2;
    const int kcB = kcA + 16;

    float4 ar[2][4];
    float acc[2][4][4] = {};

    cpa16(xsbase + kcA * 288 + ncA * 4, Bb + (size_t)kcA * NTOK + n0 + ncA);
    cpa16(xsbase + kcB * 288 + ncA * 4, Bb + (size_t)kcB * NTOK + n0 + ncA);
    CPA_COMMIT();
    #pragma unroll
    for (int i = 0; i < 4; i++) {
        int id = tid + 256 * i, m = id >> 3, c = (id & 7) << 2;
        ar[0][i] = *(const float4*)(A + (size_t)(m0 + m) * KTOT + c);
    }

    #pragma unroll
    for (int k = 0; k < NK; k++) {
        __syncthreads();
        #pragma unroll
        for (int i = 0; i < 4; i++) {
            int id = tid + 256 * i, m = id >> 3, c = (id & 7) << 2;
            float4 v = ar[k & 1][i];
            As[m][c] = rtf(v.x); As[m][c + 1] = rtf(v.y);
            As[m][c + 2] = rtf(v.z); As[m][c + 3] = rtf(v.w);
        }
        if (k + 1 < NK) {
            uint32_t bo = xsbase + ((k + 1) & 1) * 9216;
            cpa16(bo + kcA * 288 + ncA * 4, Bb + (size_t)((k + 1) * 32 + kcA) * NTOK + n0 + ncA);
            cpa16(bo + kcB * 288 + ncA * 4, Bb + (size_t)((k + 1) * 32 + kcB) * NTOK + n0 + ncA);
            CPA_COMMIT();
            #pragma unroll
            for (int i = 0; i < 4; i++) {
                int id = tid + 256 * i, m = id >> 3, c = (id & 7) << 2;
                ar[(k + 1) & 1][i] = *(const float4*)(A + (size_t)(m0 + m) * KTOT + (k + 1) * 32 + c);
            }
            asm volatile("cp.async.wait_group 1;");
        } else {
            asm volatile("cp.async.wait_group 0;");
        }
        __syncthreads();
        const float (*X)[72] = Xs[k & 1];
        #pragma unroll
        for (int ks = 0; ks < 4; ks++) {
            uint32_t a[2][4];
            #pragma unroll
            for (int mf = 0; mf < 2; mf++) {
                int r = wm + 16 * mf + g;
                a[mf][0] = __float_as_uint(As[r    ][8 * ks + t]);
                a[mf][1] = __float_as_uint(As[r + 8][8 * ks + t]);
                a[mf][2] = __float_as_uint(As[r    ][8 * ks + t + 4]);
                a[mf][3] = __float_as_uint(As[r + 8][8 * ks + t + 4]);
            }
            #pragma unroll
            for (int nf = 0; nf < 4; nf++) {
                uint32_t b0 = __float_as_uint(X[8 * ks + t    ][wn + 8 * nf + g]);
                uint32_t b1 = __float_as_uint(X[8 * ks + t + 4][wn + 8 * nf + g]);
                mma_tf32(acc[0][nf], a[0], b0, b1);
                mma_tf32(acc[1][nf], a[1], b0, b1);
            }
        }
    }

    if (OMODE == 0) {
        float* Cb = Cg + (size_t)b * MTOT * NTOK;
        #pragma unroll
        for (int mf = 0; mf < 2; mf++) {
            int row = m0 + wm + 16 * mf + g;
            float bv0 = bias[row], bv8 = bias[row + 8];
            #pragma unroll
            for (int nf = 0; nf < 4; nf++) {
                int col = n0 + wn + 8 * nf + 2 * t;
                *(float2*)(Cb + (size_t)row * NTOK + col) =
                    make_float2(acc[mf][nf][0] + bv0, acc[mf][nf][1] + bv0);
                *(float2*)(Cb + (size_t)(row + 8) * NTOK + col) =
                    make_float2(acc[mf][nf][2] + bv8, acc[mf][nf][3] + bv8);
            }
        }
    } else {
        const int sel = blockIdx.y;          // 0=Q 1=K 2=V
        if (sel == 2) {
            #pragma unroll
            for (int mf = 0; mf < 2; mf++) {
                int row = wm + 16 * mf + g;
                #pragma unroll
                for (int nf = 0; nf < 4; nf++) {
                    int col = n0 + wn + 8 * nf + 2 * t;
                    *(__half2*)&g_v[((size_t)(b * HID + row)) * NTOK + col] =
                        __floats2half2_rn(acc[mf][nf][0], acc[mf][nf][1]);
                    *(__half2*)&g_v[((size_t)(b * HID + row + 8)) * NTOK + col] =
                        __floats2half2_rn(acc[mf][nf][2], acc[mf][nf][3]);
                }
            }
        } else {
            __half* Sm = (__half*)&As[0][0];   // [tok64][136] halves, aliases As
            const float scl = (sel == 0) ? QSCL : 1.0f;
            __syncthreads();
            #pragma unroll
            for (int mf = 0; mf < 2; mf++) {
                int r = wm + 16 * mf + g;
                #pragma unroll
                for (int nf = 0; nf < 4; nf++) {
                    int c = wn + 8 * nf + 2 * t;
                    Sm[(c    ) * 136 + r    ] = __float2half_rn(acc[mf][nf][0] * scl);
                    Sm[(c + 1) * 136 + r    ] = __float2half_rn(acc[mf][nf][1] * scl);
                    Sm[(c    ) * 136 + r + 8] = __float2half_rn(acc[mf][nf][2] * scl);
                    Sm[(c + 1) * 136 + r + 8] = __float2half_rn(acc[mf][nf][3] * scl);
                }
            }
            __syncthreads();
            __half* dstb = (sel == 0) ? g_q : g_k;
            #pragma unroll
            for (int i = 0; i < 4; i++) {
                int id = tid + 256 * i;
                int tok = id >> 4;
                int mc  = id & 15;
                int hh  = mc >> 2;
                int f0  = (mc & 3) * 8;
                uint4 v = *(const uint4*)&Sm[tok * 136 + mc * 8];
                *(uint4*)(dstb + ((size_t)(b * NHEAD + hh) * NTOK + n0 + tok) * DH + f0) = v;
            }
        }
    }
}

// ================= Flash attention: f16x2 exp2, l via ones-row mma =================
// dyn SMEM (bytes):
//  buf(i) @ i*10880, i=0..2 : K [64 key][40 f] half (5120) + V [40 f][72 key] half (5760)
//     V rows 0..31 = data (re-staged); row 32 = 1.0 ones; rows 33..39 = 0 (persistent)
//  P @ 32640 : 8 warps x [16][72] half (2304 each) = 18432   -> total 51072
//  Qs @ 0 : [128 tok][40 f] half = 10240 (prologue alias)
//  Ofs @ 0 : [32 f][132 tok] float = 16896 (epilogue alias)
#define QT 128
#define KT 64
#define NTILES (NTOK / KT)
#define BUFSTRIDE 10880u
#define SMA_BYTES 51072
__global__ void __launch_bounds__(256, 3) k_attn()
{
    extern __shared__ __align__(16) char smraw[];
    __half (*Qs)[40] = (__half(*)[40])smraw;
    const uint32_t smbase = (uint32_t)__cvta_generic_to_shared(smraw);

    const int b  = blockIdx.z, h = blockIdx.y;
    const int n0 = blockIdx.x * QT;
    const int tid  = threadIdx.x;
    const int w    = tid >> 5;
    const int lane = tid & 31;
    const int grp  = lane >> 2;
    const int tg   = lane & 3;

    const __half* qg = g_q + (size_t)(b * NHEAD + h) * NTOK * DH;
    const __half* kg = g_k + (size_t)(b * NHEAD + h) * NTOK * DH;
    const __half* vg = g_v + (size_t)(b * HID + h * DH) * NTOK;

    // ---- prologue: stage Q tile [128 tok][32 f] ----
    #pragma unroll
    for (int i = 0; i < 2; i++) {
        int chunk = tid + 256 * i;
        int tok = chunk >> 2;
        int fc  = (chunk & 3) * 8;
        cpa16(smbase + (uint32_t)(tok * 80 + fc * 2), qg + (size_t)(n0 + tok) * DH + fc);
    }
    CPA_COMMIT();
    asm volatile("cp.async.wait_group 0;");
    __syncthreads();

    const int qrow = w * 16 + grp;
    uint32_t qa[2][4];
    #pragma unroll
    for (int ks = 0; ks < 2; ks++) {
        qa[ks][0] = *(const uint32_t*)&Qs[qrow    ][16 * ks + 2 * tg];
        qa[ks][1] = *(const uint32_t*)&Qs[qrow + 8][16 * ks + 2 * tg];
        qa[ks][2] = *(const uint32_t*)&Qs[qrow    ][16 * ks + 2 * tg + 8];
        qa[ks][3] = *(const uint32_t*)&Qs[qrow + 8][16 * ks + 2 * tg + 8];
    }
    __syncthreads();   // Q reads done before buffer init/staging overwrites alias

    // ---- init persistent V rows 32..39: row32 = 1.0, rows 33..39 = 0 ----
    if (tid < 216) {
        int buf = tid / 72, idx = tid % 72;
        uint4 val = (idx < 9) ? make_uint4(0x3C003C00u, 0x3C003C00u, 0x3C003C00u, 0x3C003C00u)
                              : make_uint4(0u, 0u, 0u, 0u);
        *(uint4*)(smraw + buf * BUFSTRIDE + 5120 + 32 * 144 + (idx % 9) * 16 + (idx / 9) * 144) = val;
    }

    // staging coords
    const int kkey = tid >> 2;
    const int kfc  = (tid & 3) * 8;
    const int vf   = tid >> 3;
    const int vkc  = (tid & 7) * 8;
    const uint32_t kdst = (uint32_t)(kkey * 80 + kfc * 2);
    const uint32_t vdst = 5120u + (uint32_t)(vf * 144 + vkc * 2);
    __half* Pw = (__half*)(smraw + 32640 + w * 2304);   // [16][72]

    float o[4][4] = {};
    float lc[4] = {};   // l via ones-row mma: col 32 -> c[0]/c[2] of tg==0

    #pragma unroll
    for (int p = 0; p < 2; p++) {
        const uint32_t bo = smbase + p * BUFSTRIDE;
        const int jn = p * KT;
        cpa16(bo + kdst, kg + (size_t)(jn + kkey) * DH + kfc);
        cpa16(bo + vdst, vg + (size_t)vf * NTOK + jn + vkc);
        CPA_COMMIT();
    }

    int cur = 0, wb = 2;
    for (int tIdx = 0; tIdx < NTILES; tIdx++) {
        __syncthreads();
        if (tIdx + 2 < NTILES) {
            const uint32_t bo = smbase + wb * BUFSTRIDE;
            const int jn = (tIdx + 2) * KT;
            cpa16(bo + kdst, kg + (size_t)(jn + kkey) * DH + kfc);
            cpa16(bo + vdst, vg + (size_t)vf * NTOK + jn + vkc);
            CPA_COMMIT();
            asm volatile("cp.async.wait_group 2;");
        } else if (tIdx + 1 < NTILES) {
            asm volatile("cp.async.wait_group 1;");
        } else {
            asm volatile("cp.async.wait_group 0;");
        }

        const __half (*Ks)[40] = (const __half(*)[40])(smraw + cur * BUFSTRIDE);
        const __half (*Vs)[72] = (const __half(*)[72])(smraw + cur * BUFSTRIDE + 5120);
        wb = cur;
        cur = (cur == 2) ? 0 : cur + 1;

        // ---- S = Q K^T ----
        float sc[8][4];
        #pragma unroll
        for (int nt = 0; nt < 8; nt++) {
            sc[nt][0] = sc[nt][1] = sc[nt][2] = sc[nt][3] = 0.f;
            #pragma unroll
            for (int ks = 0; ks < 2; ks++) {
                uint32_t b0 = *(const uint32_t*)&Ks[8 * nt + grp][16 * ks + 2 * tg];
                uint32_t b1 = *(const uint32_t*)&Ks[8 * nt + grp][16 * ks + 2 * tg + 8];
                mma_f16(sc[nt], qa[ks], b0, b1);
            }
        }

        // ---- p = exp2(s) via f16x2 MUFU (half the SFU ops); store fp16 P ----
        #pragma unroll
        for (int nt = 0; nt < 8; nt++) {
            __half2 h01 = __floats2half2_rn(sc[nt][0], sc[nt][1]);
            __half2 h23 = __floats2half2_rn(sc[nt][2], sc[nt][3]);
            *(__half2*)(Pw + (grp    ) * 72 + 8 * nt + 2 * tg) = h2exp2(h01);
            *(__half2*)(Pw + (grp + 8) * 72 + 8 * nt + 2 * tg) = h2exp2(h23);
        }
        __syncwarp();

        // ---- O += P V ; l += P 1 (ones row) ----
        #pragma unroll
        for (int ks2 = 0; ks2 < 4; ks2++) {
            uint32_t pa[4];
            pa[0] = *(const uint32_t*)(Pw + (grp    ) * 72 + 16 * ks2 + 2 * tg);
            pa[1] = *(const uint32_t*)(Pw + (grp + 8) * 72 + 16 * ks2 + 2 * tg);
            pa[2] = *(const uint32_t*)(Pw + (grp    ) * 72 + 16 * ks2 + 2 * tg + 8);
            pa[3] = *(const uint32_t*)(Pw + (grp + 8) * 72 + 16 * ks2 + 2 * tg + 8);
            #pragma unroll
            for (int nf = 0; nf < 4; nf++) {
                uint32_t b0 = *(const uint32_t*)&Vs[8 * nf + grp][16 * ks2 + 2 * tg];
                uint32_t b1 = *(const uint32_t*)&Vs[8 * nf + grp][16 * ks2 + 2 * tg + 8];
                mma_f16(o[nf], pa, b0, b1);
            }
            uint32_t c0 = *(const uint32_t*)&Vs[32 + grp][16 * ks2 + 2 * tg];
            uint32_t c1 = *(const uint32_t*)&Vs[32 + grp][16 * ks2 + 2 * tg + 8];
            mma_f16(lc, pa, c0, c1);
        }
    }
    __syncthreads();   // buffers free; Ofs aliases them

    // ---- l broadcast: col 32 = c[0]/c[2] of tg==0 thread of each group ----
    float l0 = __shfl_sync(0xffffffffu, lc[0], lane & ~3);
    float l1 = __shfl_sync(0xffffffffu, lc[2], lane & ~3);

    // ---- epilogue: normalize, stage [f][tok], coalesced fp32 write ----
    float inv0 = 1.0f / l0, inv1 = 1.0f / l1;
    float* Ofs = (float*)smraw;   // [32][132]
    #pragma unroll
    for (int nf = 0; nf < 4; nf++) {
        int f0 = 8 * nf + 2 * tg;
        Ofs[(f0    ) * 132 + w * 16 + grp    ] = rtf(o[nf][0] * inv0);
        Ofs[(f0 + 1) * 132 + w * 16 + grp    ] = rtf(o[nf][1] * inv0);
        Ofs[(f0    ) * 132 + w * 16 + grp + 8] = rtf(o[nf][2] * inv1);
        Ofs[(f0 + 1) * 132 + w * 16 + grp + 8] = rtf(o[nf][3] * inv1);
    }
    __syncthreads();
    float* ob = g_att + ((size_t)b * HID + h * DH) * NTOK;
    #pragma unroll
    for (int i = 0; i < 4; i++) {
        int idx4 = tid + 256 * i;
        int f  = idx4 >> 5;
        int tc = (idx4 & 31) * 4;
        float4 v = *(const float4*)&Ofs[f * 132 + tc];
        *(float4*)(ob + (size_t)f * NTOK + n0 + tc) = v;
    }
}

// ================= launch =================
extern "C" void kernel_launch(void* const* d_in, const int* in_sizes, int n_in,
                              void* d_out, int out_size)
{
    const float* x    = (const float*)d_in[0];
    const float* gw   = (const float*)d_in[1];
    const float* gb   = (const float*)d_in[2];
    const float* wqkv = (const float*)d_in[3];
    const float* wout = (const float*)d_in[4];
    const float* bout = (const float*)d_in[5];
    float* out = (float*)d_out;

    float* att = nullptr; cudaGetSymbolAddress((void**)&att, g_att);
    float* xn  = nullptr; cudaGetSymbolAddress((void**)&xn,  g_xn);

    cudaFuncSetAttribute(k_attn, cudaFuncAttributeMaxDynamicSharedMemorySize, SMA_BYTES);

    k_gnstats<<<NB * 32, 256>>>(x, gw, gb);
    k_gemm<NQKV, NC, 1><<<dim3(64, 3, NB), 256>>>(wqkv, xn, nullptr, nullptr);
    k_attn<<<dim3(NTOK / QT, NHEAD, NB), 256, SMA_BYTES>>>();
    k_gemm<NC, HID, 0><<<dim3(64, 2, NB), 256>>>(wout, att, out, bout);
}

// round 11
// speedup vs baseline: 1.0636x; 1.0636x over previous
#include <cuda_runtime.h>
#include <cuda_fp16.h>
#include <math.h>
#include <stdint.h>

#define NB    4
#define NC    256
#define NTOK  4096
#define NHEAD 4
#define DH    32
#define HID   128
#define NQKV  384
#define CPG   8

// Q pre-scale: DH^-0.5 * log2(e)
#define QSCL 0.2550662672f

// -------- scratch --------
__device__ __half g_q[(size_t)NB * NHEAD * NTOK * DH];   // [b][h][tok][f] token-major, pre-scaled
__device__ __half g_k[(size_t)NB * NHEAD * NTOK * DH];   // [b][h][tok][f] token-major
__device__ __half g_v[(size_t)NB * HID * NTOK];          // [b][f][tok]   f-major
__device__ float  g_att[(size_t)NB * HID * NTOK];        // fp32 f-major
__device__ float  g_xn [(size_t)NB * NC * NTOK];         // normalized x, rna-tf32

// ---------- helpers ----------
__device__ __forceinline__ uint32_t f2tf(float f) {
    uint32_t u; asm("cvt.rna.tf32.f32 %0, %1;" : "=r"(u) : "f"(f)); return u;
}
__device__ __forceinline__ float rtf(float f) { return __uint_as_float(f2tf(f)); }
__device__ __forceinline__ float ex2(float x) {
    float y; asm("ex2.approx.ftz.f32 %0, %1;" : "=f"(y) : "f"(x)); return y;
}
__device__ __forceinline__ void mma_tf32(float c[4], const uint32_t a[4], uint32_t b0, uint32_t b1) {
    asm volatile("mma.sync.aligned.m16n8k8.row.col.f32.tf32.tf32.f32 "
                 "{%0,%1,%2,%3}, {%4,%5,%6,%7}, {%8,%9}, {%0,%1,%2,%3};"
                 : "+f"(c[0]), "+f"(c[1]), "+f"(c[2]), "+f"(c[3])
                 : "r"(a[0]), "r"(a[1]), "r"(a[2]), "r"(a[3]), "r"(b0), "r"(b1));
}
__device__ __forceinline__ void mma_f16(float c[4], const uint32_t a[4], uint32_t b0, uint32_t b1) {
    asm volatile("mma.sync.aligned.m16n8k16.row.col.f32.f16.f16.f32 "
                 "{%0,%1,%2,%3}, {%4,%5,%6,%7}, {%8,%9}, {%0,%1,%2,%3};"
                 : "+f"(c[0]), "+f"(c[1]), "+f"(c[2]), "+f"(c[3])
                 : "r"(a[0]), "r"(a[1]), "r"(a[2]), "r"(a[3]), "r"(b0), "r"(b1));
}
__device__ __forceinline__ void ldsm_x4(uint32_t& r0, uint32_t& r1, uint32_t& r2, uint32_t& r3,
                                        uint32_t a) {
    asm volatile("ldmatrix.sync.aligned.m8n8.x4.shared.b16 {%0,%1,%2,%3}, [%4];"
                 : "=r"(r0), "=r"(r1), "=r"(r2), "=r"(r3) : "r"(a));
}
__device__ __forceinline__ void cpa16(uint32_t dst, const void* src) {
    asm volatile("cp.async.ca.shared.global [%0], [%1], 16;" :: "r"(dst), "l"(src));
}
#define CPA_COMMIT() asm volatile("cp.async.commit_group;")

// ================= GroupNorm: stats + write normalized x (rna-tf32) =================
__global__ void __launch_bounds__(256) k_gnstats(const float* __restrict__ x,
                                                 const float* __restrict__ gw,
                                                 const float* __restrict__ gb)
{
    const int b = blockIdx.x >> 5;
    const int g = blockIdx.x & 31;
    const size_t base = ((size_t)(b * NC + g * CPG)) * NTOK;
    const float4* p4 = (const float4*)(x + base);
    float4* o4 = (float4*)(g_xn + base);
    float s = 0.f, s2 = 0.f;
    for (int i = threadIdx.x; i < 8192; i += 256) {
        float4 v = p4[i];
        s  += (v.x + v.y) + (v.z + v.w);
        s2 += v.x * v.x + v.y * v.y + v.z * v.z + v.w * v.w;
    }
    #pragma unroll
    for (int off = 16; off; off >>= 1) {
        s  += __shfl_xor_sync(0xffffffffu, s,  off);
        s2 += __shfl_xor_sync(0xffffffffu, s2, off);
    }
    __shared__ float ws[8], ws2[8];
    __shared__ float al8[CPG], be8[CPG];
    const int w = threadIdx.x >> 5;
    if ((threadIdx.x & 31) == 0) { ws[w] = s; ws2[w] = s2; }
    __syncthreads();
    if (threadIdx.x < CPG) {
        float t = 0.f, t2 = 0.f;
        #pragma unroll
        for (int i = 0; i < 8; i++) { t += ws[i]; t2 += ws2[i]; }
        float mean = t * (1.f / 32768.f);
        float var  = t2 * (1.f / 32768.f) - mean * mean;
        float sr = rsqrtf(var + 1e-5f);
        int c = g * CPG + threadIdx.x;
        float a = gw[c] * sr;
        al8[threadIdx.x] = a;
        be8[threadIdx.x] = gb[c] - mean * a;
    }
    __syncthreads();
    for (int i = threadIdx.x; i < 8192; i += 256) {
        int cl = i >> 10;
        float a = al8[cl], bb = be8[cl];
        float4 v = p4[i];
        o4[i] = make_float4(rtf(fmaf(v.x, a, bb)), rtf(fmaf(v.y, a, bb)),
                            rtf(fmaf(v.z, a, bb)), rtf(fmaf(v.w, a, bb)));
    }
}

// ================= pipelined tf32 GEMM (unchanged) =================
template<int MTOT, int KTOT, int OMODE>
__global__ void __launch_bounds__(256) k_gemm(const float* __restrict__ A,
                                              const float* __restrict__ Bg,
                                              float* __restrict__ Cg,
                                              const float* __restrict__ bias)
{
    constexpr int NK = KTOT / 32;
    const int b  = blockIdx.z;
    const int m0 = blockIdx.y * 128;
    const int n0 = blockIdx.x * 64;
    __shared__ float As[128][36];
    __shared__ float Xs[2][32][72];
    const float* Bb = Bg + (size_t)b * KTOT * NTOK;
    const int tid = threadIdx.x, w = tid >> 5, lane = tid & 31;
    const int g = lane >> 2, t = lane & 3;
    const int wm = (w >> 1) * 32, wn = (w & 1) * 32;
    const uint32_t xsbase = (uint32_t)__cvta_generic_to_shared(&Xs[0][0][0]);
    const int kcA = tid >> 4, ncA = (tid & 15) << 2;
    const int kcB = kcA + 16;

    float4 ar[2][4];
    float acc[2][4][4] = {};

    cpa16(xsbase + kcA * 288 + ncA * 4, Bb + (size_t)kcA * NTOK + n0 + ncA);
    cpa16(xsbase + kcB * 288 + ncA * 4, Bb + (size_t)kcB * NTOK + n0 + ncA);
    CPA_COMMIT();
    #pragma unroll
    for (int i = 0; i < 4; i++) {
        int id = tid + 256 * i, m = id >> 3, c = (id & 7) << 2;
        ar[0][i] = *(const float4*)(A + (size_t)(m0 + m) * KTOT + c);
    }

    #pragma unroll
    for (int k = 0; k < NK; k++) {
        __syncthreads();
        #pragma unroll
        for (int i = 0; i < 4; i++) {
            int id = tid + 256 * i, m = id >> 3, c = (id & 7) << 2;
            float4 v = ar[k & 1][i];
            As[m][c] = rtf(v.x); As[m][c + 1] = rtf(v.y);
            As[m][c + 2] = rtf(v.z); As[m][c + 3] = rtf(v.w);
        }
        if (k + 1 < NK) {
            uint32_t bo = xsbase + ((k + 1) & 1) * 9216;
            cpa16(bo + kcA * 288 + ncA * 4, Bb + (size_t)((k + 1) * 32 + kcA) * NTOK + n0 + ncA);
            cpa16(bo + kcB * 288 + ncA * 4, Bb + (size_t)((k + 1) * 32 + kcB) * NTOK + n0 + ncA);
            CPA_COMMIT();
            #pragma unroll
            for (int i = 0; i < 4; i++) {
                int id = tid + 256 * i, m = id >> 3, c = (id & 7) << 2;
                ar[(k + 1) & 1][i] = *(const float4*)(A + (size_t)(m0 + m) * KTOT + (k + 1) * 32 + c);
            }
            asm volatile("cp.async.wait_group 1;");
        } else {
            asm volatile("cp.async.wait_group 0;");
        }
        __syncthreads();
        const float (*X)[72] = Xs[k & 1];
        #pragma unroll
        for (int ks = 0; ks < 4; ks++) {
            uint32_t a[2][4];
            #pragma unroll
            for (int mf = 0; mf < 2; mf++) {
                int r = wm + 16 * mf + g;
                a[mf][0] = __float_as_uint(As[r    ][8 * ks + t]);
                a[mf][1] = __float_as_uint(As[r + 8][8 * ks + t]);
                a[mf][2] = __float_as_uint(As[r    ][8 * ks + t + 4]);
                a[mf][3] = __float_as_uint(As[r + 8][8 * ks + t + 4]);
            }
            #pragma unroll
            for (int nf = 0; nf < 4; nf++) {
                uint32_t b0 = __float_as_uint(X[8 * ks + t    ][wn + 8 * nf + g]);
                uint32_t b1 = __float_as_uint(X[8 * ks + t + 4][wn + 8 * nf + g]);
                mma_tf32(acc[0][nf], a[0], b0, b1);
                mma_tf32(acc[1][nf], a[1], b0, b1);
            }
        }
    }

    if (OMODE == 0) {
        float* Cb = Cg + (size_t)b * MTOT * NTOK;
        #pragma unroll
        for (int mf = 0; mf < 2; mf++) {
            int row = m0 + wm + 16 * mf + g;
            float bv0 = bias[row], bv8 = bias[row + 8];
            #pragma unroll
            for (int nf = 0; nf < 4; nf++) {
                int col = n0 + wn + 8 * nf + 2 * t;
                *(float2*)(Cb + (size_t)row * NTOK + col) =
                    make_float2(acc[mf][nf][0] + bv0, acc[mf][nf][1] + bv0);
                *(float2*)(Cb + (size_t)(row + 8) * NTOK + col) =
                    make_float2(acc[mf][nf][2] + bv8, acc[mf][nf][3] + bv8);
            }
        }
    } else {
        const int sel = blockIdx.y;          // 0=Q 1=K 2=V
        if (sel == 2) {
            #pragma unroll
            for (int mf = 0; mf < 2; mf++) {
                int row = wm + 16 * mf + g;
                #pragma unroll
                for (int nf = 0; nf < 4; nf++) {
                    int col = n0 + wn + 8 * nf + 2 * t;
                    *(__half2*)&g_v[((size_t)(b * HID + row)) * NTOK + col] =
                        __floats2half2_rn(acc[mf][nf][0], acc[mf][nf][1]);
                    *(__half2*)&g_v[((size_t)(b * HID + row + 8)) * NTOK + col] =
                        __floats2half2_rn(acc[mf][nf][2], acc[mf][nf][3]);
                }
            }
        } else {
            __half* Sm = (__half*)&As[0][0];   // [tok64][136] halves, aliases As
            const float scl = (sel == 0) ? QSCL : 1.0f;
            __syncthreads();
            #pragma unroll
            for (int mf = 0; mf < 2; mf++) {
                int r = wm + 16 * mf + g;
                #pragma unroll
                for (int nf = 0; nf < 4; nf++) {
                    int c = wn + 8 * nf + 2 * t;
                    Sm[(c    ) * 136 + r    ] = __float2half_rn(acc[mf][nf][0] * scl);
                    Sm[(c + 1) * 136 + r    ] = __float2half_rn(acc[mf][nf][1] * scl);
                    Sm[(c    ) * 136 + r + 8] = __float2half_rn(acc[mf][nf][2] * scl);
                    Sm[(c + 1) * 136 + r + 8] = __float2half_rn(acc[mf][nf][3] * scl);
                }
            }
            __syncthreads();
            __half* dstb = (sel == 0) ? g_q : g_k;
            #pragma unroll
            for (int i = 0; i < 4; i++) {
                int id = tid + 256 * i;
                int tok = id >> 4;
                int mc  = id & 15;
                int hh  = mc >> 2;
                int f0  = (mc & 3) * 8;
                uint4 v = *(const uint4*)&Sm[tok * 136 + mc * 8];
                *(uint4*)(dstb + ((size_t)(b * NHEAD + hh) * NTOK + n0 + tok) * DH + f0) = v;
            }
        }
    }
}

// ================= Flash attention: ldmatrix fragments, fp32 exp2, deferred l =================
// dyn SMEM (bytes):
//  buf(i) @ i*9728, i=0..2 : K [64 key][40 f] half (5120) + V [32 f][72 key] half (4608)
//  P @ 29184 : 8 warps x [16][72] half (2304 each) = 18432   -> total 47616
//  Qs @ 0 : [128 tok][40 f] half = 10240 (prologue alias)
//  Ofs @ 0 : [32 f][132 tok] float = 16896 (epilogue alias)
#define QT 128
#define KT 64
#define NTILES (NTOK / KT)
#define BUFSTRIDE 9728u
#define SMA_BYTES 47616
__global__ void __launch_bounds__(256, 3) k_attn()
{
    extern __shared__ __align__(16) char smraw[];
    __half (*Qs)[40] = (__half(*)[40])smraw;
    const uint32_t smbase = (uint32_t)__cvta_generic_to_shared(smraw);

    const int b  = blockIdx.z, h = blockIdx.y;
    const int n0 = blockIdx.x * QT;
    const int tid  = threadIdx.x;
    const int w    = tid >> 5;
    const int lane = tid & 31;
    const int grp  = lane >> 2;
    const int tg   = lane & 3;

    const __half* qg = g_q + (size_t)(b * NHEAD + h) * NTOK * DH;
    const __half* kg = g_k + (size_t)(b * NHEAD + h) * NTOK * DH;
    const __half* vg = g_v + (size_t)(b * HID + h * DH) * NTOK;

    // ---- prologue: stage Q tile [128 tok][32 f] ----
    #pragma unroll
    for (int i = 0; i < 2; i++) {
        int chunk = tid + 256 * i;
        int tok = chunk >> 2;
        int fc  = (chunk & 3) * 8;
        cpa16(smbase + (uint32_t)(tok * 80 + fc * 2), qg + (size_t)(n0 + tok) * DH + fc);
    }
    CPA_COMMIT();
    asm volatile("cp.async.wait_group 0;");
    __syncthreads();

    const int qrow = w * 16 + grp;
    uint32_t qa[2][4];
    #pragma unroll
    for (int ks = 0; ks < 2; ks++) {
        qa[ks][0] = *(const uint32_t*)&Qs[qrow    ][16 * ks + 2 * tg];
        qa[ks][1] = *(const uint32_t*)&Qs[qrow + 8][16 * ks + 2 * tg];
        qa[ks][2] = *(const uint32_t*)&Qs[qrow    ][16 * ks + 2 * tg + 8];
        qa[ks][3] = *(const uint32_t*)&Qs[qrow + 8][16 * ks + 2 * tg + 8];
    }
    __syncthreads();   // Q reads done before staging overwrites alias

    // cp.async staging coords
    const int kkey = tid >> 2;
    const int kfc  = (tid & 3) * 8;
    const int vf   = tid >> 3;
    const int vkc  = (tid & 7) * 8;
    const uint32_t kdst = (uint32_t)(kkey * 80 + kfc * 2);
    const uint32_t vdst = 5120u + (uint32_t)(vf * 144 + vkc * 2);
    __half* Pw = (__half*)(smraw + 29184 + w * 2304);   // [16][72]
    const uint32_t pwbase = smbase + 29184u + (uint32_t)w * 2304u;

    // ldmatrix per-thread offsets (all conflict-free by pitch math: 80B and 144B)
    const int r8 = lane & 7;
    // QK B: tiles at f-chunks 0,8,16,24 ; rows = key 8nt+r8
    const uint32_t offQK = (uint32_t)(r8 * 80 + (lane >> 3) * 16);
    // PV A (P): t0 rows0-7 k0 | t1 rows8-15 k0 | t2 rows0-7 k8 | t3 rows8-15 k8
    const uint32_t offPA = (uint32_t)((r8 + ((lane >> 3) & 1) * 8) * 144 + (lane >> 4) * 16);
    // PV B (V): t0 f0-7,k0 | t1 f0-7,k8 | t2 f8-15,k0 | t3 f8-15,k8 (fgroup = lane>>4)
    const uint32_t offV0 = (uint32_t)((((lane >> 4) & 1) * 8 + r8) * 144 + ((lane >> 3) & 1) * 16);

    float o[4][4] = {};
    float l0p = 0.f, l1p = 0.f;

    #pragma unroll
    for (int p = 0; p < 2; p++) {
        const uint32_t bo = smbase + p * BUFSTRIDE;
        const int jn = p * KT;
        cpa16(bo + kdst, kg + (size_t)(jn + kkey) * DH + kfc);
        cpa16(bo + vdst, vg + (size_t)vf * NTOK + jn + vkc);
        CPA_COMMIT();
    }

    int cur = 0, wb = 2;
    for (int tIdx = 0; tIdx < NTILES; tIdx++) {
        __syncthreads();
        if (tIdx + 2 < NTILES) {
            const uint32_t bo = smbase + wb * BUFSTRIDE;
            const int jn = (tIdx + 2) * KT;
            cpa16(bo + kdst, kg + (size_t)(jn + kkey) * DH + kfc);
            cpa16(bo + vdst, vg + (size_t)vf * NTOK + jn + vkc);
            CPA_COMMIT();
            asm volatile("cp.async.wait_group 2;");
        } else if (tIdx + 1 < NTILES) {
            asm volatile("cp.async.wait_group 1;");
        } else {
            asm volatile("cp.async.wait_group 0;");
        }

        const uint32_t kbuf = smbase + cur * BUFSTRIDE;
        const uint32_t vbuf = kbuf + 5120u;
        wb = cur;
        cur = (cur == 2) ? 0 : cur + 1;

        // ---- S = Q K^T : 8 LDSM.x4 + 16 HMMA ----
        float sc[8][4];
        #pragma unroll
        for (int nt = 0; nt < 8; nt++) {
            uint32_t b0, b1, b2, b3;
            ldsm_x4(b0, b1, b2, b3, kbuf + offQK + 640u * nt);
            sc[nt][0] = sc[nt][1] = sc[nt][2] = sc[nt][3] = 0.f;
            mma_f16(sc[nt], qa[0], b0, b1);
            mma_f16(sc[nt], qa[1], b2, b3);
        }

        // ---- p = exp2(s); l partials fp32; store fp16 P ----
        #pragma unroll
        for (int nt = 0; nt < 8; nt++) {
            float p0 = ex2(sc[nt][0]);
            float p1 = ex2(sc[nt][1]);
            float p2 = ex2(sc[nt][2]);
            float p3 = ex2(sc[nt][3]);
            l0p += p0 + p1;
            l1p += p2 + p3;
            *(__half2*)(Pw + (grp    ) * 72 + 8 * nt + 2 * tg) = __floats2half2_rn(p0, p1);
            *(__half2*)(Pw + (grp + 8) * 72 + 8 * nt + 2 * tg) = __floats2half2_rn(p2, p3);
        }
        __syncwarp();

        // ---- O += P V : per ks2: 1 LDSM.x4 (P) + 2 LDSM.x4 (V) + 4 HMMA ----
        #pragma unroll
        for (int ks2 = 0; ks2 < 4; ks2++) {
            uint32_t pa[4];
            ldsm_x4(pa[0], pa[1], pa[2], pa[3], pwbase + offPA + 32u * ks2);
            uint32_t v0, v1, v2, v3, v4, v5, v6, v7;
            ldsm_x4(v0, v1, v2, v3, vbuf + offV0 + 32u * ks2);            // nf 0,1
            ldsm_x4(v4, v5, v6, v7, vbuf + offV0 + 2304u + 32u * ks2);    // nf 2,3
            mma_f16(o[0], pa, v0, v1);
            mma_f16(o[1], pa, v2, v3);
            mma_f16(o[2], pa, v4, v5);
            mma_f16(o[3], pa, v6, v7);
        }
    }
    __syncthreads();   // buffers free; Ofs aliases them

    // ---- reduce l across the 4 threads of each row group (once) ----
    l0p += __shfl_xor_sync(0xffffffffu, l0p, 1);
    l0p += __shfl_xor_sync(0xffffffffu, l0p, 2);
    l1p += __shfl_xor_sync(0xffffffffu, l1p, 1);
    l1p += __shfl_xor_sync(0xffffffffu, l1p, 2);

    // ---- epilogue: normalize, stage [f][tok], coalesced fp32 write ----
    float inv0 = 1.0f / l0p, inv1 = 1.0f / l1p;
    float* Ofs = (float*)smraw;   // [32][132]
    #pragma unroll
    for (int nf = 0; nf < 4; nf++) {
        int f0 = 8 * nf + 2 * tg;
        Ofs[(f0    ) * 132 + w * 16 + grp    ] = rtf(o[nf][0] * inv0);
        Ofs[(f0 + 1) * 132 + w * 16 + grp    ] = rtf(o[nf][1] * inv0);
        Ofs[(f0    ) * 132 + w * 16 + grp + 8] = rtf(o[nf][2] * inv1);
        Ofs[(f0 + 1) * 132 + w * 16 + grp + 8] = rtf(o[nf][3] * inv1);
    }
    __syncthreads();
    float* ob = g_att + ((size_t)b * HID + h * DH) * NTOK;
    #pragma unroll
    for (int i = 0; i < 4; i++) {
        int idx4 = tid + 256 * i;
        int f  = idx4 >> 5;
        int tc = (idx4 & 31) * 4;
        float4 v = *(const float4*)&Ofs[f * 132 + tc];
        *(float4*)(ob + (size_t)f * NTOK + n0 + tc) = v;
    }
}

// ================= launch =================
extern "C" void kernel_launch(void* const* d_in, const int* in_sizes, int n_in,
                              void* d_out, int out_size)
{
    const float* x    = (const float*)d_in[0];
    const float* gw   = (const float*)d_in[1];
    const float* gb   = (const float*)d_in[2];
    const float* wqkv = (const float*)d_in[3];
    const float* wout = (const float*)d_in[4];
    const float* bout = (const float*)d_in[5];
    float* out = (float*)d_out;

    float* att = nullptr; cudaGetSymbolAddress((void**)&att, g_att);
    float* xn  = nullptr; cudaGetSymbolAddress((void**)&xn,  g_xn);

    cudaFuncSetAttribute(k_attn, cudaFuncAttributeMaxDynamicSharedMemorySize, SMA_BYTES);

    k_gnstats<<<NB * 32, 256>>>(x, gw, gb);
    k_gemm<NQKV, NC, 1><<<dim3(64, 3, NB), 256>>>(wqkv, xn, nullptr, nullptr);
    k_attn<<<dim3(NTOK / QT, NHEAD, NB), 256, SMA_BYTES>>>();
    k_gemm<NC, HID, 0><<<dim3(64, 2, NB), 256>>>(wout, att, out, bout);
}

// round 12
// speedup vs baseline: 1.0915x; 1.0263x over previous
#include <cuda_runtime.h>
#include <cuda_fp16.h>
#include <math.h>
#include <stdint.h>

#define NB    4
#define NC    256
#define NTOK  4096
#define NHEAD 4
#define DH    32
#define HID   128
#define NQKV  384
#define CPG   8

// Q pre-scale: DH^-0.5 * log2(e)
#define QSCL 0.2550662672f

// -------- scratch --------
__device__ __half g_q[(size_t)NB * NHEAD * NTOK * DH];   // [b][h][tok][f] token-major, pre-scaled
__device__ __half g_k[(size_t)NB * NHEAD * NTOK * DH];   // [b][h][tok][f] token-major
__device__ __half g_v[(size_t)NB * HID * NTOK];          // [b][f][tok]   f-major
__device__ float  g_att[(size_t)NB * HID * NTOK];        // fp32 f-major
__device__ float  g_xn [(size_t)NB * NC * NTOK];         // normalized x, rna-tf32

// ---------- helpers ----------
__device__ __forceinline__ uint32_t f2tf(float f) {
    uint32_t u; asm("cvt.rna.tf32.f32 %0, %1;" : "=r"(u) : "f"(f)); return u;
}
__device__ __forceinline__ float rtf(float f) { return __uint_as_float(f2tf(f)); }
__device__ __forceinline__ float ex2(float x) {
    float y; asm("ex2.approx.ftz.f32 %0, %1;" : "=f"(y) : "f"(x)); return y;
}
__device__ __forceinline__ void mma_tf32(float c[4], const uint32_t a[4], uint32_t b0, uint32_t b1) {
    asm volatile("mma.sync.aligned.m16n8k8.row.col.f32.tf32.tf32.f32 "
                 "{%0,%1,%2,%3}, {%4,%5,%6,%7}, {%8,%9}, {%0,%1,%2,%3};"
                 : "+f"(c[0]), "+f"(c[1]), "+f"(c[2]), "+f"(c[3])
                 : "r"(a[0]), "r"(a[1]), "r"(a[2]), "r"(a[3]), "r"(b0), "r"(b1));
}
__device__ __forceinline__ void mma_f16(float c[4], const uint32_t a[4], uint32_t b0, uint32_t b1) {
    asm volatile("mma.sync.aligned.m16n8k16.row.col.f32.f16.f16.f32 "
                 "{%0,%1,%2,%3}, {%4,%5,%6,%7}, {%8,%9}, {%0,%1,%2,%3};"
                 : "+f"(c[0]), "+f"(c[1]), "+f"(c[2]), "+f"(c[3])
                 : "r"(a[0]), "r"(a[1]), "r"(a[2]), "r"(a[3]), "r"(b0), "r"(b1));
}
__device__ __forceinline__ void ldsm_x4(uint32_t& r0, uint32_t& r1, uint32_t& r2, uint32_t& r3,
                                        uint32_t a) {
    asm volatile("ldmatrix.sync.aligned.m8n8.x4.shared.b16 {%0,%1,%2,%3}, [%4];"
                 : "=r"(r0), "=r"(r1), "=r"(r2), "=r"(r3) : "r"(a));
}
__device__ __forceinline__ void cpa16(uint32_t dst, const void* src) {
    asm volatile("cp.async.ca.shared.global [%0], [%1], 16;" :: "r"(dst), "l"(src));
}
#define CPA_COMMIT() asm volatile("cp.async.commit_group;")

// ================= GroupNorm: stats + write normalized x (rna-tf32) =================
__global__ void __launch_bounds__(256) k_gnstats(const float* __restrict__ x,
                                                 const float* __restrict__ gw,
                                                 const float* __restrict__ gb)
{
    const int b = blockIdx.x >> 5;
    const int g = blockIdx.x & 31;
    const size_t base = ((size_t)(b * NC + g * CPG)) * NTOK;
    const float4* p4 = (const float4*)(x + base);
    float4* o4 = (float4*)(g_xn + base);
    float s = 0.f, s2 = 0.f;
    for (int i = threadIdx.x; i < 8192; i += 256) {
        float4 v = p4[i];
        s  += (v.x + v.y) + (v.z + v.w);
        s2 += v.x * v.x + v.y * v.y + v.z * v.z + v.w * v.w;
    }
    #pragma unroll
    for (int off = 16; off; off >>= 1) {
        s  += __shfl_xor_sync(0xffffffffu, s,  off);
        s2 += __shfl_xor_sync(0xffffffffu, s2, off);
    }
    __shared__ float ws[8], ws2[8];
    __shared__ float al8[CPG], be8[CPG];
    const int w = threadIdx.x >> 5;
    if ((threadIdx.x & 31) == 0) { ws[w] = s; ws2[w] = s2; }
    __syncthreads();
    if (threadIdx.x < CPG) {
        float t = 0.f, t2 = 0.f;
        #pragma unroll
        for (int i = 0; i < 8; i++) { t += ws[i]; t2 += ws2[i]; }
        float mean = t * (1.f / 32768.f);
        float var  = t2 * (1.f / 32768.f) - mean * mean;
        float sr = rsqrtf(var + 1e-5f);
        int c = g * CPG + threadIdx.x;
        float a = gw[c] * sr;
        al8[threadIdx.x] = a;
        be8[threadIdx.x] = gb[c] - mean * a;
    }
    __syncthreads();
    for (int i = threadIdx.x; i < 8192; i += 256) {
        int cl = i >> 10;
        float a = al8[cl], bb = be8[cl];
        float4 v = p4[i];
        o4[i] = make_float4(rtf(fmaf(v.x, a, bb)), rtf(fmaf(v.y, a, bb)),
                            rtf(fmaf(v.z, a, bb)), rtf(fmaf(v.w, a, bb)));
    }
}

// ================= pipelined tf32 GEMM (unchanged) =================
template<int MTOT, int KTOT, int OMODE>
__global__ void __launch_bounds__(256) k_gemm(const float* __restrict__ A,
                                              const float* __restrict__ Bg,
                                              float* __restrict__ Cg,
                                              const float* __restrict__ bias)
{
    constexpr int NK = KTOT / 32;
    const int b  = blockIdx.z;
    const int m0 = blockIdx.y * 128;
    const int n0 = blockIdx.x * 64;
    __shared__ float As[128][36];
    __shared__ float Xs[2][32][72];
    const float* Bb = Bg + (size_t)b * KTOT * NTOK;
    const int tid = threadIdx.x, w = tid >> 5, lane = tid & 31;
    const int g = lane >> 2, t = lane & 3;
    const int wm = (w >> 1) * 32, wn = (w & 1) * 32;
    const uint32_t xsbase = (uint32_t)__cvta_generic_to_shared(&Xs[0][0][0]);
    const int kcA = tid >> 4, ncA = (tid & 15) << 2;
    const int kcB = kcA + 16;

    float4 ar[2][4];
    float acc[2][4][4] = {};

    cpa16(xsbase + kcA * 288 + ncA * 4, Bb + (size_t)kcA * NTOK + n0 + ncA);
    cpa16(xsbase + kcB * 288 + ncA * 4, Bb + (size_t)kcB * NTOK + n0 + ncA);
    CPA_COMMIT();
    #pragma unroll
    for (int i = 0; i < 4; i++) {
        int id = tid + 256 * i, m = id >> 3, c = (id & 7) << 2;
        ar[0][i] = *(const float4*)(A + (size_t)(m0 + m) * KTOT + c);
    }

    #pragma unroll
    for (int k = 0; k < NK; k++) {
        __syncthreads();
        #pragma unroll
        for (int i = 0; i < 4; i++) {
            int id = tid + 256 * i, m = id >> 3, c = (id & 7) << 2;
            float4 v = ar[k & 1][i];
            As[m][c] = rtf(v.x); As[m][c + 1] = rtf(v.y);
            As[m][c + 2] = rtf(v.z); As[m][c + 3] = rtf(v.w);
        }
        if (k + 1 < NK) {
            uint32_t bo = xsbase + ((k + 1) & 1) * 9216;
            cpa16(bo + kcA * 288 + ncA * 4, Bb + (size_t)((k + 1) * 32 + kcA) * NTOK + n0 + ncA);
            cpa16(bo + kcB * 288 + ncA * 4, Bb + (size_t)((k + 1) * 32 + kcB) * NTOK + n0 + ncA);
            CPA_COMMIT();
            #pragma unroll
            for (int i = 0; i < 4; i++) {
                int id = tid + 256 * i, m = id >> 3, c = (id & 7) << 2;
                ar[(k + 1) & 1][i] = *(const float4*)(A + (size_t)(m0 + m) * KTOT + (k + 1) * 32 + c);
            }
            asm volatile("cp.async.wait_group 1;");
        } else {
            asm volatile("cp.async.wait_group 0;");
        }
        __syncthreads();
        const float (*X)[72] = Xs[k & 1];
        #pragma unroll
        for (int ks = 0; ks < 4; ks++) {
            uint32_t a[2][4];
            #pragma unroll
            for (int mf = 0; mf < 2; mf++) {
                int r = wm + 16 * mf + g;
                a[mf][0] = __float_as_uint(As[r    ][8 * ks + t]);
                a[mf][1] = __float_as_uint(As[r + 8][8 * ks + t]);
                a[mf][2] = __float_as_uint(As[r    ][8 * ks + t + 4]);
                a[mf][3] = __float_as_uint(As[r + 8][8 * ks + t + 4]);
            }
            #pragma unroll
            for (int nf = 0; nf < 4; nf++) {
                uint32_t b0 = __float_as_uint(X[8 * ks + t    ][wn + 8 * nf + g]);
                uint32_t b1 = __float_as_uint(X[8 * ks + t + 4][wn + 8 * nf + g]);
                mma_tf32(acc[0][nf], a[0], b0, b1);
                mma_tf32(acc[1][nf], a[1], b0, b1);
            }
        }
    }

    if (OMODE == 0) {
        float* Cb = Cg + (size_t)b * MTOT * NTOK;
        #pragma unroll
        for (int mf = 0; mf < 2; mf++) {
            int row = m0 + wm + 16 * mf + g;
            float bv0 = bias[row], bv8 = bias[row + 8];
            #pragma unroll
            for (int nf = 0; nf < 4; nf++) {
                int col = n0 + wn + 8 * nf + 2 * t;
                *(float2*)(Cb + (size_t)row * NTOK + col) =
                    make_float2(acc[mf][nf][0] + bv0, acc[mf][nf][1] + bv0);
                *(float2*)(Cb + (size_t)(row + 8) * NTOK + col) =
                    make_float2(acc[mf][nf][2] + bv8, acc[mf][nf][3] + bv8);
            }
        }
    } else {
        const int sel = blockIdx.y;          // 0=Q 1=K 2=V
        if (sel == 2) {
            #pragma unroll
            for (int mf = 0; mf < 2; mf++) {
                int row = wm + 16 * mf + g;
                #pragma unroll
                for (int nf = 0; nf < 4; nf++) {
                    int col = n0 + wn + 8 * nf + 2 * t;
                    *(__half2*)&g_v[((size_t)(b * HID + row)) * NTOK + col] =
                        __floats2half2_rn(acc[mf][nf][0], acc[mf][nf][1]);
                    *(__half2*)&g_v[((size_t)(b * HID + row + 8)) * NTOK + col] =
                        __floats2half2_rn(acc[mf][nf][2], acc[mf][nf][3]);
                }
            }
        } else {
            __half* Sm = (__half*)&As[0][0];   // [tok64][136] halves, aliases As
            const float scl = (sel == 0) ? QSCL : 1.0f;
            __syncthreads();
            #pragma unroll
            for (int mf = 0; mf < 2; mf++) {
                int r = wm + 16 * mf + g;
                #pragma unroll
                for (int nf = 0; nf < 4; nf++) {
                    int c = wn + 8 * nf + 2 * t;
                    Sm[(c    ) * 136 + r    ] = __float2half_rn(acc[mf][nf][0] * scl);
                    Sm[(c + 1) * 136 + r    ] = __float2half_rn(acc[mf][nf][1] * scl);
                    Sm[(c    ) * 136 + r + 8] = __float2half_rn(acc[mf][nf][2] * scl);
                    Sm[(c + 1) * 136 + r + 8] = __float2half_rn(acc[mf][nf][3] * scl);
                }
            }
            __syncthreads();
            __half* dstb = (sel == 0) ? g_q : g_k;
            #pragma unroll
            for (int i = 0; i < 4; i++) {
                int id = tid + 256 * i;
                int tok = id >> 4;
                int mc  = id & 15;
                int hh  = mc >> 2;
                int f0  = (mc & 3) * 8;
                uint4 v = *(const uint4*)&Sm[tok * 136 + mc * 8];
                *(uint4*)(dstb + ((size_t)(b * NHEAD + hh) * NTOK + n0 + tok) * DH + f0) = v;
            }
        }
    }
}

// ================= Flash attention: 4-buffer, sync every 2 tiles =================
// dyn SMEM (bytes):
//  buf(i) @ i*9728, i=0..3 : K [64 key][40 f] half (5120) + V [32 f][72 key] half (4608)
//  P @ 38912 : 8 warps x [16][72] half (2304 each) = 18432   -> total 57344
//  Qs @ 0 : [128 tok][40 f] half = 10240 (prologue alias)
//  Ofs @ 0 : [32 f][132 tok] float = 16896 (epilogue alias)
#define QT 128
#define KT 64
#define NTILES (NTOK / KT)
#define BUFSTRIDE 9728u
#define SMA_BYTES 57344
__global__ void __launch_bounds__(256, 3) k_attn()
{
    extern __shared__ __align__(16) char smraw[];
    __half (*Qs)[40] = (__half(*)[40])smraw;
    const uint32_t smbase = (uint32_t)__cvta_generic_to_shared(smraw);

    const int b  = blockIdx.z, h = blockIdx.y;
    const int n0 = blockIdx.x * QT;
    const int tid  = threadIdx.x;
    const int w    = tid >> 5;
    const int lane = tid & 31;
    const int grp  = lane >> 2;
    const int tg   = lane & 3;

    const __half* qg = g_q + (size_t)(b * NHEAD + h) * NTOK * DH;
    const __half* kg = g_k + (size_t)(b * NHEAD + h) * NTOK * DH;
    const __half* vg = g_v + (size_t)(b * HID + h * DH) * NTOK;

    // ---- prologue: stage Q tile [128 tok][32 f] ----
    #pragma unroll
    for (int i = 0; i < 2; i++) {
        int chunk = tid + 256 * i;
        int tok = chunk >> 2;
        int fc  = (chunk & 3) * 8;
        cpa16(smbase + (uint32_t)(tok * 80 + fc * 2), qg + (size_t)(n0 + tok) * DH + fc);
    }
    CPA_COMMIT();
    asm volatile("cp.async.wait_group 0;");
    __syncthreads();

    const int qrow = w * 16 + grp;
    uint32_t qa[2][4];
    #pragma unroll
    for (int ks = 0; ks < 2; ks++) {
        qa[ks][0] = *(const uint32_t*)&Qs[qrow    ][16 * ks + 2 * tg];
        qa[ks][1] = *(const uint32_t*)&Qs[qrow + 8][16 * ks + 2 * tg];
        qa[ks][2] = *(const uint32_t*)&Qs[qrow    ][16 * ks + 2 * tg + 8];
        qa[ks][3] = *(const uint32_t*)&Qs[qrow + 8][16 * ks + 2 * tg + 8];
    }
    __syncthreads();   // Q reads done before staging overwrites alias

    // cp.async staging coords
    const int kkey = tid >> 2;
    const int kfc  = (tid & 3) * 8;
    const int vf   = tid >> 3;
    const int vkc  = (tid & 7) * 8;
    const uint32_t kdst = (uint32_t)(kkey * 80 + kfc * 2);
    const uint32_t vdst = 5120u + (uint32_t)(vf * 144 + vkc * 2);
    __half* Pw = (__half*)(smraw + 38912 + w * 2304);   // [16][72]
    const uint32_t pwbase = smbase + 38912u + (uint32_t)w * 2304u;

    // ldmatrix per-thread offsets (conflict-free: pitches 80B / 144B)
    const int r8 = lane & 7;
    const uint32_t offQK = (uint32_t)(r8 * 80 + (lane >> 3) * 16);
    const uint32_t offPA = (uint32_t)((r8 + ((lane >> 3) & 1) * 8) * 144 + (lane >> 4) * 16);
    const uint32_t offV0 = (uint32_t)((((lane >> 4) & 1) * 8 + r8) * 144 + ((lane >> 3) & 1) * 16);

    float o[4][4] = {};
    float l0p = 0.f, l1p = 0.f;

    auto stage = [&](int t) {
        const uint32_t bo = smbase + (uint32_t)(t & 3) * BUFSTRIDE;
        const int jn = t * KT;
        cpa16(bo + kdst, kg + (size_t)(jn + kkey) * DH + kfc);
        cpa16(bo + vdst, vg + (size_t)vf * NTOK + jn + vkc);
        CPA_COMMIT();
    };

    auto process = [&](int t) {
        const uint32_t kbuf = smbase + (uint32_t)(t & 3) * BUFSTRIDE;
        const uint32_t vbuf = kbuf + 5120u;

        // ---- S = Q K^T : 8 LDSM.x4 + 16 HMMA ----
        float sc[8][4];
        #pragma unroll
        for (int nt = 0; nt < 8; nt++) {
            uint32_t b0, b1, b2, b3;
            ldsm_x4(b0, b1, b2, b3, kbuf + offQK + 640u * nt);
            sc[nt][0] = sc[nt][1] = sc[nt][2] = sc[nt][3] = 0.f;
            mma_f16(sc[nt], qa[0], b0, b1);
            mma_f16(sc[nt], qa[1], b2, b3);
        }

        // ---- p = exp2(s); l partials fp32; store fp16 P ----
        __syncwarp();   // prev tile's P LDSM reads complete before overwrite
        #pragma unroll
        for (int nt = 0; nt < 8; nt++) {
            float p0 = ex2(sc[nt][0]);
            float p1 = ex2(sc[nt][1]);
            float p2 = ex2(sc[nt][2]);
            float p3 = ex2(sc[nt][3]);
            l0p += p0 + p1;
            l1p += p2 + p3;
            *(__half2*)(Pw + (grp    ) * 72 + 8 * nt + 2 * tg) = __floats2half2_rn(p0, p1);
            *(__half2*)(Pw + (grp + 8) * 72 + 8 * nt + 2 * tg) = __floats2half2_rn(p2, p3);
        }
        __syncwarp();

        // ---- O += P V ----
        #pragma unroll
        for (int ks2 = 0; ks2 < 4; ks2++) {
            uint32_t pa[4];
            ldsm_x4(pa[0], pa[1], pa[2], pa[3], pwbase + offPA + 32u * ks2);
            uint32_t v0, v1, v2, v3, v4, v5, v6, v7;
            ldsm_x4(v0, v1, v2, v3, vbuf + offV0 + 32u * ks2);
            ldsm_x4(v4, v5, v6, v7, vbuf + offV0 + 2304u + 32u * ks2);
            mma_f16(o[0], pa, v0, v1);
            mma_f16(o[1], pa, v2, v3);
            mma_f16(o[2], pa, v4, v5);
            mma_f16(o[3], pa, v6, v7);
        }
    };

    // prefetch tiles 0,1
    stage(0);
    stage(1);

    for (int pt = 0; pt < NTILES / 2; pt++) {
        const int t0 = 2 * pt;
        __syncthreads();   // all warps done reading the pair we are about to overwrite
        if (t0 + 2 < NTILES) {
            stage(t0 + 2);
            stage(t0 + 3);
            asm volatile("cp.async.wait_group 2;");
        } else {
            asm volatile("cp.async.wait_group 0;");
        }
        process(t0);
        process(t0 + 1);
    }
    __syncthreads();   // buffers free; Ofs aliases them

    // ---- reduce l across the 4 threads of each row group (once) ----
    l0p += __shfl_xor_sync(0xffffffffu, l0p, 1);
    l0p += __shfl_xor_sync(0xffffffffu, l0p, 2);
    l1p += __shfl_xor_sync(0xffffffffu, l1p, 1);
    l1p += __shfl_xor_sync(0xffffffffu, l1p, 2);

    // ---- epilogue: normalize, stage [f][tok], coalesced fp32 write ----
    float inv0 = 1.0f / l0p, inv1 = 1.0f / l1p;
    float* Ofs = (float*)smraw;   // [32][132]
    #pragma unroll
    for (int nf = 0; nf < 4; nf++) {
        int f0 = 8 * nf + 2 * tg;
        Ofs[(f0    ) * 132 + w * 16 + grp    ] = rtf(o[nf][0] * inv0);
        Ofs[(f0 + 1) * 132 + w * 16 + grp    ] = rtf(o[nf][1] * inv0);
        Ofs[(f0    ) * 132 + w * 16 + grp + 8] = rtf(o[nf][2] * inv1);
        Ofs[(f0 + 1) * 132 + w * 16 + grp + 8] = rtf(o[nf][3] * inv1);
    }
    __syncthreads();
    float* ob = g_att + ((size_t)b * HID + h * DH) * NTOK;
    #pragma unroll
    for (int i = 0; i < 4; i++) {
        int idx4 = tid + 256 * i;
        int f  = idx4 >> 5;
        int tc = (idx4 & 31) * 4;
        float4 v = *(const float4*)&Ofs[f * 132 + tc];
        *(float4*)(ob + (size_t)f * NTOK + n0 + tc) = v;
    }
}

// ================= launch =================
extern "C" void kernel_launch(void* const* d_in, const int* in_sizes, int n_in,
                              void* d_out, int out_size)
{
    const float* x    = (const float*)d_in[0];
    const float* gw   = (const float*)d_in[1];
    const float* gb   = (const float*)d_in[2];
    const float* wqkv = (const float*)d_in[3];
    const float* wout = (const float*)d_in[4];
    const float* bout = (const float*)d_in[5];
    float* out = (float*)d_out;

    float* att = nullptr; cudaGetSymbolAddress((void**)&att, g_att);
    float* xn  = nullptr; cudaGetSymbolAddress((void**)&xn,  g_xn);

    cudaFuncSetAttribute(k_attn, cudaFuncAttributeMaxDynamicSharedMemorySize, SMA_BYTES);

    k_gnstats<<<NB * 32, 256>>>(x, gw, gb);
    k_gemm<NQKV, NC, 1><<<dim3(64, 3, NB), 256>>>(wqkv, xn, nullptr, nullptr);
    k_attn<<<dim3(NTOK / QT, NHEAD, NB), 256, SMA_BYTES>>>();
    k_gemm<NC, HID, 0><<<dim3(64, 2, NB), 256>>>(wout, att, out, bout);
}